// round 2
// baseline (speedup 1.0000x reference)
#include <cuda_runtime.h>
#include <math.h>

// Problem constants
#define BB 2
#define NN 1024
#define HH 128
#define WW 128
#define BN (BB*NN)
#define HWPX (HH*WW)
#define CHUNK 128

#define C0_SH 0.28209479177387814f
#define EXP_M10 4.5399929762484854e-05f  // exp(-10)

// ---------- scratch (no allocations allowed) ----------
__device__ float  g_par[BN*12];        // unsorted per-gaussian params (AoS, 12 floats)
__device__ float4 g_sorted4[BN*3];     // z-sorted params, 3x float4 per gaussian
__device__ float  g_zkey[BN];
__device__ float  g_rgb[BB*3*HWPX];    // rendered rgb (clipped)
__device__ float  g_depthimg[BB*HWPX]; // rendered depth
__device__ double g_acc[4];            // l1_rgb_sum, ssim_sum, l1_depth_sum, opac_reg_sum

// params layout per gaussian (12 floats):
// [0]=px [1]=py [2]=inv00 [3]=inv01 [4]=inv11 [5]=cr [6]=cg [7]=cb [8]=z [9]=opac [10]=a0 [11]=pad

__global__ void zero_acc_kernel() {
    if (threadIdx.x < 4) g_acc[threadIdx.x] = 0.0;
}

__device__ __forceinline__ void block_reduce_to(double* target, float v, float* sdata) {
    int tid = threadIdx.x;
    sdata[tid] = v;
    __syncthreads();
    for (int s = blockDim.x >> 1; s > 0; s >>= 1) {
        if (tid < s) sdata[tid] += sdata[tid + s];
        __syncthreads();
    }
    if (tid == 0) atomicAdd(target, (double)sdata[0]);
}

// ---------- 1. per-gaussian preprocessing + opacity entropy ----------
__global__ void prep_kernel(const float* __restrict__ gs, const float* __restrict__ intr) {
    __shared__ float sred[256];
    int i = blockIdx.x * blockDim.x + threadIdx.x;   // i < BN by construction
    int b = i / NN;
    const float* g = gs + (size_t)i * 38;

    float fx = intr[b*9 + 0], fy = intr[b*9 + 4];
    float cx = intr[b*9 + 2], cy = intr[b*9 + 5];

    float mx = g[0], my = g[1], mz = g[2];
    float sx = g[3], sy = g[4], sz = g[5];
    float qw = g[6], qx = g[7], qy = g[8], qz = g[9];
    float op = g[10];

    float z = fmaxf(mz, 1e-4f);
    float px = fx * mx / z + cx;
    float py = fy * my / z + cy;

    // rotation matrix
    float R00 = 1.f - 2.f*(qy*qy + qz*qz);
    float R01 = 2.f*(qx*qy - qw*qz);
    float R02 = 2.f*(qx*qz + qw*qy);
    float R10 = 2.f*(qx*qy + qw*qz);
    float R11 = 1.f - 2.f*(qx*qx + qz*qz);
    float R12 = 2.f*(qy*qz - qw*qx);
    float R20 = 2.f*(qx*qz - qw*qy);
    float R21 = 2.f*(qy*qz + qw*qx);
    float R22 = 1.f - 2.f*(qx*qx + qy*qy);

    // RS = R * diag(s) (scale columns)
    float RS00 = R00*sx, RS01 = R01*sy, RS02 = R02*sz;
    float RS10 = R10*sx, RS11 = R11*sy, RS12 = R12*sz;
    float RS20 = R20*sx, RS21 = R21*sy, RS22 = R22*sz;

    float zc  = fmaxf(mz, 1e-6f);
    float zsq = zc * zc;
    float J00 = fx / zc;
    float J02 = -fx * mx / zsq;
    float J11 = fy / zc;
    float J12 = -fy * my / zsq;

    // M = J * RS  (2x3)
    float M00 = J00*RS00 + J02*RS20;
    float M01 = J00*RS01 + J02*RS21;
    float M02 = J00*RS02 + J02*RS22;
    float M10 = J11*RS10 + J12*RS20;
    float M11 = J11*RS11 + J12*RS21;
    float M12 = J11*RS12 + J12*RS22;

    float c00 = M00*M00 + M01*M01 + M02*M02 + 0.3f;
    float c01 = M00*M10 + M01*M11 + M02*M12;
    float c11 = M10*M10 + M11*M11 + M12*M12 + 0.3f;

    float det = fmaxf(c00*c11 - c01*c01, 1e-8f);
    float inv00 = c11 / det;
    float inv11 = c00 / det;
    float inv01 = -c01 / det;

    float cr = fminf(fmaxf(g[11]*C0_SH + 0.5f, 0.f), 1.f);
    float cg = fminf(fmaxf(g[12]*C0_SH + 0.5f, 0.f), 1.f);
    float cb = fminf(fmaxf(g[13]*C0_SH + 0.5f, 0.f), 1.f);

    float a0 = EXP_M10 * op;

    float* p = g_par + i*12;
    p[0]=px; p[1]=py; p[2]=inv00; p[3]=inv01; p[4]=inv11;
    p[5]=cr; p[6]=cg; p[7]=cb; p[8]=z; p[9]=op; p[10]=a0; p[11]=0.f;
    g_zkey[i] = z;

    // opacity entropy regularizer (uses raw channel 10, clipped)
    float o = fminf(fmaxf(op, 1e-6f), 1.f - 1e-6f);
    float ent = -(o*logf(o) + (1.f-o)*logf(1.f-o));
    block_reduce_to(&g_acc[3], ent, sred);
}

// ---------- 2. per-batch bitonic sort by z + gather sorted params ----------
__global__ void sort_kernel() {
    __shared__ float key[NN];
    __shared__ int   idx[NN];
    int tid = threadIdx.x;
    int b = blockIdx.x;
    key[tid] = g_zkey[b*NN + tid];
    idx[tid] = tid;
    __syncthreads();

    for (int k = 2; k <= NN; k <<= 1) {
        for (int j = k >> 1; j > 0; j >>= 1) {
            int ixj = tid ^ j;
            if (ixj > tid) {
                bool up = ((tid & k) == 0);
                float a = key[tid], c = key[ixj];
                if ((a > c) == up) {
                    key[tid] = c; key[ixj] = a;
                    int t = idx[tid]; idx[tid] = idx[ixj]; idx[ixj] = t;
                }
            }
            __syncthreads();
        }
    }

    // gather
    const float* src = g_par + (size_t)(b*NN + idx[tid]) * 12;
    float* dst = (float*)(g_sorted4 + (size_t)(b*NN + tid) * 3);
    #pragma unroll
    for (int f = 0; f < 12; f++) dst[f] = src[f];
}

// ---------- 3. dense front-to-back compositing ----------
__global__ void __launch_bounds__(256) render_kernel() {
    __shared__ float4 sbuf[CHUNK*3];   // 6 KB
    int p   = blockIdx.x * 256 + threadIdx.x;   // 0 .. B*H*W-1
    int b   = p >> 14;                          // /16384
    int rem = p & 16383;
    int y   = rem >> 7;
    int x   = rem & 127;
    float xf = (float)x, yf = (float)y;

    float T = 1.f, rr = 0.f, gg = 0.f, bb = 0.f, dep = 0.f;
    const float4* src = g_sorted4 + (size_t)b * NN * 3;

    for (int base = 0; base < NN; base += CHUNK) {
        __syncthreads();
        for (int i = threadIdx.x; i < CHUNK*3; i += 256)
            sbuf[i] = src[base*3 + i];
        __syncthreads();

        const float* sp = (const float*)sbuf;
        #pragma unroll 4
        for (int gi = 0; gi < CHUNK; gi++) {
            const float* gp = sp + gi*12;
            float dx = xf - gp[0];
            float dy = yf - gp[1];
            float q  = gp[2]*dx*dx + 2.f*gp[3]*dx*dy + gp[4]*dy*dy;
            float power = fminf(-0.5f*q, 0.f);
            float a;
            if (power > -10.f) a = __expf(power) * gp[9];
            else               a = gp[10];               // exp(-10)*opac precomputed
            a = fminf(a, 0.99f);
            float w = T * a;
            rr  += w * gp[5];
            gg  += w * gp[6];
            bb  += w * gp[7];
            dep += w * gp[8];
            T   *= (1.f - a);
        }
    }

    int pix = y*WW + x;
    g_rgb[((size_t)(b*3 + 0))*HWPX + pix] = fminf(fmaxf(rr, 0.f), 1.f);
    g_rgb[((size_t)(b*3 + 1))*HWPX + pix] = fminf(fmaxf(gg, 0.f), 1.f);
    g_rgb[((size_t)(b*3 + 2))*HWPX + pix] = fminf(fmaxf(bb, 0.f), 1.f);
    g_depthimg[(size_t)b*HWPX + pix] = dep;
}

// ---------- 4. SSIM + L1 losses ----------
__global__ void loss_kernel(const float* __restrict__ tgt_rgb,
                            const float* __restrict__ tgt_depth) {
    __shared__ float sred[256];
    int p   = blockIdx.x * 256 + threadIdx.x;
    int b   = p >> 14;
    int rem = p & 16383;
    int y   = rem >> 7;
    int x   = rem & 127;
    int pix = y*WW + x;

    // 7-tap gaussian window (sigma=1.5), normalized
    float wg[7]; float ws = 0.f;
    #pragma unroll
    for (int i = 0; i < 7; i++) { float c = (float)(i-3); wg[i] = __expf(-c*c/4.5f); ws += wg[i]; }
    #pragma unroll
    for (int i = 0; i < 7; i++) wg[i] /= ws;

    const float SC1 = 1e-4f, SC2 = 9e-4f;

    float l1d = fabsf(g_depthimg[(size_t)b*HWPX + pix] - tgt_depth[(size_t)b*HWPX + pix]);

    float l1rgb = 0.f, ssim = 0.f;
    #pragma unroll
    for (int c = 0; c < 3; c++) {
        const float* im1 = g_rgb  + ((size_t)(b*3 + c))*HWPX;
        const float* im2 = tgt_rgb + ((size_t)(b*3 + c))*HWPX;
        l1rgb += fabsf(im1[pix] - im2[pix]);

        float mu1=0.f, mu2=0.f, e11=0.f, e22=0.f, e12=0.f;
        #pragma unroll
        for (int dy2 = -3; dy2 <= 3; dy2++) {
            int yy = y + dy2;
            if (yy < 0 || yy >= HH) continue;   // zero padding
            float wy = wg[dy2+3];
            #pragma unroll
            for (int dx2 = -3; dx2 <= 3; dx2++) {
                int xx = x + dx2;
                if (xx < 0 || xx >= WW) continue;
                float w = wy * wg[dx2+3];
                float a1 = im1[yy*WW + xx];
                float a2 = im2[yy*WW + xx];
                mu1 += w*a1; mu2 += w*a2;
                e11 += w*a1*a1; e22 += w*a2*a2; e12 += w*a1*a2;
            }
        }
        float s1  = e11 - mu1*mu1;
        float s2  = e22 - mu2*mu2;
        float s12 = e12 - mu1*mu2;
        ssim += (2.f*mu1*mu2 + SC1) * (2.f*s12 + SC2) /
                ((mu1*mu1 + mu2*mu2 + SC1) * (s1 + s2 + SC2));
    }

    block_reduce_to(&g_acc[0], l1rgb, sred);
    block_reduce_to(&g_acc[1], ssim,  sred);
    block_reduce_to(&g_acc[2], l1d,   sred);
}

// ---------- 5. final scalar ----------
__global__ void finalize_kernel(float* __restrict__ out) {
    double l1_rgb   = g_acc[0] / (double)(BB*3*HWPX);
    double ssim_val = g_acc[1] / (double)(BB*3*HWPX);
    double l1_depth = g_acc[2] / (double)(BB*HWPX);
    double opac_reg = g_acc[3] / (double)(BB*NN);
    out[0] = (float)(0.8*l1_rgb + 0.2*(1.0 - ssim_val) + 0.5*l1_depth + 0.01*opac_reg);
}

extern "C" void kernel_launch(void* const* d_in, const int* in_sizes, int n_in,
                              void* d_out, int out_size) {
    const float* gaussians = (const float*)d_in[0];
    const float* intr      = (const float*)d_in[1];
    const float* tgt_rgb   = (const float*)d_in[2];
    const float* tgt_depth = (const float*)d_in[3];
    float* out = (float*)d_out;

    zero_acc_kernel<<<1, 4>>>();
    prep_kernel<<<BN/256, 256>>>(gaussians, intr);
    sort_kernel<<<BB, NN>>>();
    render_kernel<<<BB*HWPX/256, 256>>>();
    loss_kernel<<<BB*HWPX/256, 256>>>(tgt_rgb, tgt_depth);
    finalize_kernel<<<1, 1>>>(out);
}

// round 5
// speedup vs baseline: 2.4403x; 2.4403x over previous
#include <cuda_runtime.h>
#include <math.h>

// Problem constants
#define BB 2
#define NN 1024
#define HH 128
#define WW 128
#define BN (BB*NN)
#define HWPX (HH*WW)

#define C0_SH 0.28209479177387814f
#define EXP_M10 4.5399929762484854e-05f   // exp(-10)
#define LOG2E 1.4426950408889634f
#define P2_CUT (-14.4269504f)             // -10 * log2(e)

// tiles: 8x4 pixels per warp-tile; 16 x 32 = 512 tiles per batch
#define TILES_PER_B 512
#define NWORDS 32                          // 1024 gaussians / 32
#define NSEG 4
#define SEG_LEN (NN/NSEG)                  // 256
#define SEG_WORDS (NWORDS/NSEG)            // 8

// mask kernel: one warp per (b, word, tile-group-of-32)
#define MASK_WARPS (BB*NWORDS*(TILES_PER_B/32))   // 2*32*16 = 1024
#define MASK_BLOCKS (MASK_WARPS*32/256)           // 128

// ---------- scratch (no allocations allowed) ----------
__device__ float    g_par[BN*12];          // unsorted per-gaussian params
__device__ float4   g_sorted4[BN*3];       // z-sorted params, 3x float4 per gaussian
__device__ float4   g_geo[BN];             // sorted (px, py, R2, 0)
__device__ float    g_zkey[BN];
__device__ unsigned g_mask[BB*NWORDS*TILES_PER_B];   // [b][word][tile]
__device__ float4   g_pfxS[BB][NN+1];      // prefix color/depth aggregate
__device__ float    g_pfxP[BB][NN+1];      // prefix transmittance product
__device__ float    g_rgb[BB*3*HWPX];
__device__ float    g_depthimg[BB*HWPX];
__device__ double   g_acc[4];              // l1_rgb, ssim, l1_depth, opac_reg

// params layout per gaussian (12 floats):
// [0]=px [1]=py [2]=e0 [3]=e1 [4]=e2 [5]=cr [6]=cg [7]=cb [8]=z [9]=opac [10]=a0 [11]=R2
// where power_log2 = e0*dx^2 + e1*dx*dy + e2*dy^2  (e* include -0.5*log2e folding)

__global__ void zero_acc_kernel() {
    if (threadIdx.x < 4) g_acc[threadIdx.x] = 0.0;
}

__device__ __forceinline__ void block_reduce_to(double* target, float v, float* sdata) {
    int tid = threadIdx.x;
    sdata[tid] = v;
    __syncthreads();
    for (int s = blockDim.x >> 1; s > 0; s >>= 1) {
        if (tid < s) sdata[tid] += sdata[tid + s];
        __syncthreads();
    }
    if (tid == 0) atomicAdd(target, (double)sdata[0]);
}

// ---------- 1. per-gaussian preprocessing + opacity entropy ----------
__global__ void prep_kernel(const float* __restrict__ gs, const float* __restrict__ intr) {
    __shared__ float sred[256];
    int i = blockIdx.x * blockDim.x + threadIdx.x;
    int b = i / NN;
    const float* g = gs + (size_t)i * 38;

    float fx = intr[b*9 + 0], fy = intr[b*9 + 4];
    float cx = intr[b*9 + 2], cy = intr[b*9 + 5];

    float mx = g[0], my = g[1], mz = g[2];
    float sx = g[3], sy = g[4], sz = g[5];
    float qw = g[6], qx = g[7], qy = g[8], qz = g[9];
    float op = g[10];

    float z = fmaxf(mz, 1e-4f);
    float px = fx * mx / z + cx;
    float py = fy * my / z + cy;

    float R00 = 1.f - 2.f*(qy*qy + qz*qz);
    float R01 = 2.f*(qx*qy - qw*qz);
    float R02 = 2.f*(qx*qz + qw*qy);
    float R10 = 2.f*(qx*qy + qw*qz);
    float R11 = 1.f - 2.f*(qx*qx + qz*qz);
    float R12 = 2.f*(qy*qz - qw*qx);
    float R20 = 2.f*(qx*qz - qw*qy);
    float R21 = 2.f*(qy*qz + qw*qx);
    float R22 = 1.f - 2.f*(qx*qx + qy*qy);

    float RS00 = R00*sx, RS01 = R01*sy, RS02 = R02*sz;
    float RS10 = R10*sx, RS11 = R11*sy, RS12 = R12*sz;
    float RS20 = R20*sx, RS21 = R21*sy, RS22 = R22*sz;

    float zc  = fmaxf(mz, 1e-6f);
    float zsq = zc * zc;
    float J00 = fx / zc;
    float J02 = -fx * mx / zsq;
    float J11 = fy / zc;
    float J12 = -fy * my / zsq;

    float M00 = J00*RS00 + J02*RS20;
    float M01 = J00*RS01 + J02*RS21;
    float M02 = J00*RS02 + J02*RS22;
    float M10 = J11*RS10 + J12*RS20;
    float M11 = J11*RS11 + J12*RS21;
    float M12 = J11*RS12 + J12*RS22;

    float c00 = M00*M00 + M01*M01 + M02*M02 + 0.3f;
    float c01 = M00*M10 + M01*M11 + M02*M12;
    float c11 = M10*M10 + M11*M11 + M12*M12 + 0.3f;

    float detRaw = c00*c11 - c01*c01;
    float det = fmaxf(detRaw, 1e-8f);
    float inv00 = c11 / det;
    float inv11 = c00 / det;
    float inv01 = -c01 / det;

    // conic with folded -0.5*log2e (and the 2x on the cross term)
    float e0 = -0.5f * LOG2E * inv00;
    float e1 = -LOG2E * inv01;
    float e2 = -0.5f * LOG2E * inv11;

    // conservative cull radius: power < -10 guaranteed outside R
    // Q = d' * Sigma^-1 * d >= |d|^2 / lambda_max(cov2d)
    float trC = c00 + c11;
    float discC = sqrtf(fmaxf(trC*trC - 4.f*detRaw, 0.f));
    float lmaxC = 0.5f * (trC + discC);
    float R2 = 20.f * lmaxC * 1.01f + 1.f;

    float cr = fminf(fmaxf(g[11]*C0_SH + 0.5f, 0.f), 1.f);
    float cg = fminf(fmaxf(g[12]*C0_SH + 0.5f, 0.f), 1.f);
    float cb = fminf(fmaxf(g[13]*C0_SH + 0.5f, 0.f), 1.f);

    float a0 = EXP_M10 * op;

    float* p = g_par + i*12;
    p[0]=px; p[1]=py; p[2]=e0; p[3]=e1; p[4]=e2;
    p[5]=cr; p[6]=cg; p[7]=cb; p[8]=z; p[9]=op; p[10]=a0; p[11]=R2;
    g_zkey[i] = z;

    float o = fminf(fmaxf(op, 1e-6f), 1.f - 1e-6f);
    float ent = -(o*logf(o) + (1.f-o)*logf(1.f-o));
    block_reduce_to(&g_acc[3], ent, sred);
}

// ---------- 2. per-batch bitonic sort by z + gather sorted params ----------
__global__ void sort_kernel() {
    __shared__ float key[NN];
    __shared__ int   idx[NN];
    int tid = threadIdx.x;
    int b = blockIdx.x;
    key[tid] = g_zkey[b*NN + tid];
    idx[tid] = tid;
    __syncthreads();

    for (int k = 2; k <= NN; k <<= 1) {
        for (int j = k >> 1; j > 0; j >>= 1) {
            int ixj = tid ^ j;
            if (ixj > tid) {
                bool up = ((tid & k) == 0);
                float a = key[tid], c = key[ixj];
                if ((a > c) == up) {
                    key[tid] = c; key[ixj] = a;
                    int t = idx[tid]; idx[tid] = idx[ixj]; idx[ixj] = t;
                }
            }
            __syncthreads();
        }
    }

    const float* src = g_par + (size_t)(b*NN + idx[tid]) * 12;
    float* dst = (float*)(g_sorted4 + (size_t)(b*NN + tid) * 3);
    #pragma unroll
    for (int f = 0; f < 12; f++) dst[f] = src[f];
    g_geo[b*NN + tid] = make_float4(src[0], src[1], src[11], 0.f);
}

// ---------- 3. prefix scan of far-field (constant-alpha) aggregates ----------
// P[i] = prod_{k<i}(1-a0_k);  S[i] = sum_{k<i} P[k]*a0_k*(cr,cg,cb,z)_k
// One warp per batch; lane l owns gaussians [l*32, l*32+32).
__global__ void prefix_kernel() {
    int b = blockIdx.x;
    int l = threadIdx.x;            // 0..31
    const float4* par = g_sorted4 + (size_t)b * NN * 3;
    int base = l * 32;

    // pass 1: local affine aggregate (T -> T*p, C -> C + T*s)
    float p = 1.f;
    float sr=0.f, sg=0.f, sb=0.f, sd=0.f;
    for (int k = 0; k < 32; k++) {
        int i = base + k;
        float4 fb = par[i*3+1];
        float4 fc = par[i*3+2];
        float a0 = fc.z;
        float w = p * a0;
        sr += w * fb.y; sg += w * fb.z; sb += w * fb.w; sd += w * fc.x;
        p *= (1.f - a0);
    }
    // inclusive scan across lanes (compose: earlier-first)
    for (int off = 1; off < 32; off <<= 1) {
        float pp  = __shfl_up_sync(0xffffffffu, p, off);
        float xr  = __shfl_up_sync(0xffffffffu, sr, off);
        float xg  = __shfl_up_sync(0xffffffffu, sg, off);
        float xb  = __shfl_up_sync(0xffffffffu, sb, off);
        float xd  = __shfl_up_sync(0xffffffffu, sd, off);
        if (l >= off) {
            sr = xr + pp * sr; sg = xg + pp * sg;
            sb = xb + pp * sb; sd = xd + pp * sd;
            p = pp * p;
        }
    }
    // exclusive start for this lane
    float Pe = __shfl_up_sync(0xffffffffu, p, 1);
    float Er = __shfl_up_sync(0xffffffffu, sr, 1);
    float Eg = __shfl_up_sync(0xffffffffu, sg, 1);
    float Eb = __shfl_up_sync(0xffffffffu, sb, 1);
    float Ed = __shfl_up_sync(0xffffffffu, sd, 1);
    if (l == 0) { Pe = 1.f; Er = Eg = Eb = Ed = 0.f; }

    // pass 2: write prefixes
    float P = Pe;
    float4 S = make_float4(Er, Eg, Eb, Ed);
    for (int k = 0; k < 32; k++) {
        int i = base + k;
        g_pfxP[b][i] = P;
        g_pfxS[b][i] = S;
        float4 fb = par[i*3+1];
        float4 fc = par[i*3+2];
        float a0 = fc.z;
        float w = P * a0;
        S.x += w * fb.y; S.y += w * fb.z; S.z += w * fb.w; S.w += w * fc.x;
        P *= (1.f - a0);
    }
    if (l == 31) { g_pfxP[b][NN] = P; g_pfxS[b][NN] = S; }
}

// ---------- 4. per-tile activity bitmasks ----------
// warp handles (b, word, tile-group-of-32); lane = tile within group.
__global__ void mask_kernel() {
    int t = blockIdx.x * 256 + threadIdx.x;
    int gw = t >> 5, lane = t & 31;
    int b = gw >> 9;
    int rem = gw & 511;
    int word = rem >> 4;
    int grp = rem & 15;
    int tile = grp * 32 + lane;

    float x0 = (float)((tile & 15) * 8);
    float x1 = x0 + 7.f;
    float y0 = (float)((tile >> 4) * 4);
    float y1 = y0 + 3.f;

    const float4* geo = g_geo + (size_t)b * NN;
    unsigned m = 0;
    #pragma unroll 4
    for (int k = 0; k < 32; k++) {
        float4 ge = geo[word*32 + k];       // broadcast across warp
        float ex = fmaxf(fmaxf(x0 - ge.x, ge.x - x1), 0.f);
        float ey = fmaxf(fmaxf(y0 - ge.y, ge.y - y1), 0.f);
        if (ex*ex + ey*ey <= ge.z) m |= (1u << k);
    }
    g_mask[(b*NWORDS + word)*TILES_PER_B + tile] = m;
}

// ---------- 5. sparse compositing: warp=(tile, depth segment) ----------
__global__ void __launch_bounds__(128) render_kernel() {
    int b    = blockIdx.x >> 9;
    int tile = blockIdx.x & 511;
    int wid  = threadIdx.x >> 5;   // segment 0..3
    int lane = threadIdx.x & 31;

    int xpix = (tile & 15) * 8 + (lane & 7);
    int ypix = (tile >> 4) * 4 + (lane >> 3);
    float xf = (float)xpix, yf = (float)ypix;

    const float4* par = g_sorted4 + (size_t)b * NN * 3;
    const float4* Spfx = g_pfxS[b];
    const float*  Ppfx = g_pfxP[b];

    float T = 1.f, rr = 0.f, gg = 0.f, bbl = 0.f, dep = 0.f;
    int cur = wid * SEG_LEN;

    #pragma unroll 1
    for (int w = wid * SEG_WORDS; w < wid * SEG_WORDS + SEG_WORDS; w++) {
        unsigned m = g_mask[(b*NWORDS + w)*TILES_PER_B + tile];
        while (m) {
            int bit = __ffs(m) - 1;
            m &= m - 1;
            int j = (w << 5) + bit;
            if (j > cur) {   // culled run [cur, j): apply prefix aggregate
                float4 Si = Spfx[cur], Sj = Spfx[j];
                float f = __fdividef(T, Ppfx[cur]);
                rr  += f * (Sj.x - Si.x);
                gg  += f * (Sj.y - Si.y);
                bbl += f * (Sj.z - Si.z);
                dep += f * (Sj.w - Si.w);
                T = f * Ppfx[j];
            }
            // full evaluation of gaussian j
            float4 A  = par[j*3];
            float4 Bq = par[j*3+1];
            float4 Cq = par[j*3+2];
            float dx = xf - A.x, dy = yf - A.y;
            float p2 = A.z * dx * dx;
            p2 = fmaf(A.w, dx*dy, p2);
            p2 = fmaf(Bq.x, dy*dy, p2);
            p2 = fminf(p2, 0.f);
            float a;
            if (p2 > P2_CUT) {
                float e;
                asm("ex2.approx.ftz.f32 %0, %1;" : "=f"(e) : "f"(p2));
                a = fminf(e * Cq.y, 0.99f);
            } else {
                a = Cq.z;      // exp(-10)*opac
            }
            float wgt = T * a;
            rr  = fmaf(wgt, Bq.y, rr);
            gg  = fmaf(wgt, Bq.z, gg);
            bbl = fmaf(wgt, Bq.w, bbl);
            dep = fmaf(wgt, Cq.x, dep);
            T  -= wgt;
            cur = j + 1;
        }
    }
    int send = wid * SEG_LEN + SEG_LEN;
    if (cur < send) {
        float4 Si = Spfx[cur], Sj = Spfx[send];
        float f = __fdividef(T, Ppfx[cur]);
        rr  += f * (Sj.x - Si.x);
        gg  += f * (Sj.y - Si.y);
        bbl += f * (Sj.z - Si.z);
        dep += f * (Sj.w - Si.w);
        T = f * Ppfx[send];
    }

    // combine 4 depth segments (front-to-back)
    __shared__ float4 sC[NSEG][32];
    __shared__ float  sT[NSEG][32];
    sC[wid][lane] = make_float4(rr, gg, bbl, dep);
    sT[wid][lane] = T;
    __syncthreads();

    if (wid == 0) {
        float4 Cc = sC[0][lane];
        float  Tt = sT[0][lane];
        #pragma unroll
        for (int s = 1; s < NSEG; s++) {
            float4 Cs = sC[s][lane];
            Cc.x += Tt * Cs.x; Cc.y += Tt * Cs.y;
            Cc.z += Tt * Cs.z; Cc.w += Tt * Cs.w;
            Tt *= sT[s][lane];
        }
        int pix = ypix * WW + xpix;
        g_rgb[((size_t)(b*3 + 0))*HWPX + pix] = fminf(fmaxf(Cc.x, 0.f), 1.f);
        g_rgb[((size_t)(b*3 + 1))*HWPX + pix] = fminf(fmaxf(Cc.y, 0.f), 1.f);
        g_rgb[((size_t)(b*3 + 2))*HWPX + pix] = fminf(fmaxf(Cc.z, 0.f), 1.f);
        g_depthimg[(size_t)b*HWPX + pix] = Cc.w;
    }
}

// ---------- 6. SSIM + L1 losses ----------
__global__ void loss_kernel(const float* __restrict__ tgt_rgb,
                            const float* __restrict__ tgt_depth) {
    __shared__ float sred[256];
    int p   = blockIdx.x * 256 + threadIdx.x;
    int b   = p >> 14;
    int rem = p & 16383;
    int y   = rem >> 7;
    int x   = rem & 127;
    int pix = y*WW + x;

    float wg[7]; float ws = 0.f;
    #pragma unroll
    for (int i = 0; i < 7; i++) { float c = (float)(i-3); wg[i] = __expf(-c*c/4.5f); ws += wg[i]; }
    #pragma unroll
    for (int i = 0; i < 7; i++) wg[i] /= ws;

    const float SC1 = 1e-4f, SC2 = 9e-4f;

    float l1d = fabsf(g_depthimg[(size_t)b*HWPX + pix] - tgt_depth[(size_t)b*HWPX + pix]);

    float l1rgb = 0.f, ssim = 0.f;
    #pragma unroll
    for (int c = 0; c < 3; c++) {
        const float* im1 = g_rgb  + ((size_t)(b*3 + c))*HWPX;
        const float* im2 = tgt_rgb + ((size_t)(b*3 + c))*HWPX;
        l1rgb += fabsf(im1[pix] - im2[pix]);

        float mu1=0.f, mu2=0.f, e11=0.f, e22=0.f, e12=0.f;
        #pragma unroll
        for (int dy2 = -3; dy2 <= 3; dy2++) {
            int yy = y + dy2;
            if (yy < 0 || yy >= HH) continue;
            float wy = wg[dy2+3];
            #pragma unroll
            for (int dx2 = -3; dx2 <= 3; dx2++) {
                int xx = x + dx2;
                if (xx < 0 || xx >= WW) continue;
                float w = wy * wg[dx2+3];
                float a1 = im1[yy*WW + xx];
                float a2 = im2[yy*WW + xx];
                mu1 += w*a1; mu2 += w*a2;
                e11 += w*a1*a1; e22 += w*a2*a2; e12 += w*a1*a2;
            }
        }
        float s1  = e11 - mu1*mu1;
        float s2  = e22 - mu2*mu2;
        float s12 = e12 - mu1*mu2;
        ssim += (2.f*mu1*mu2 + SC1) * (2.f*s12 + SC2) /
                ((mu1*mu1 + mu2*mu2 + SC1) * (s1 + s2 + SC2));
    }

    block_reduce_to(&g_acc[0], l1rgb, sred);
    block_reduce_to(&g_acc[1], ssim,  sred);
    block_reduce_to(&g_acc[2], l1d,   sred);
}

// ---------- 7. final scalar ----------
__global__ void finalize_kernel(float* __restrict__ out) {
    double l1_rgb   = g_acc[0] / (double)(BB*3*HWPX);
    double ssim_val = g_acc[1] / (double)(BB*3*HWPX);
    double l1_depth = g_acc[2] / (double)(BB*HWPX);
    double opac_reg = g_acc[3] / (double)(BB*NN);
    out[0] = (float)(0.8*l1_rgb + 0.2*(1.0 - ssim_val) + 0.5*l1_depth + 0.01*opac_reg);
}

extern "C" void kernel_launch(void* const* d_in, const int* in_sizes, int n_in,
                              void* d_out, int out_size) {
    const float* gaussians = (const float*)d_in[0];
    const float* intr      = (const float*)d_in[1];
    const float* tgt_rgb   = (const float*)d_in[2];
    const float* tgt_depth = (const float*)d_in[3];
    float* out = (float*)d_out;

    zero_acc_kernel<<<1, 4>>>();
    prep_kernel<<<BN/256, 256>>>(gaussians, intr);
    sort_kernel<<<BB, NN>>>();
    prefix_kernel<<<BB, 32>>>();
    mask_kernel<<<MASK_BLOCKS, 256>>>();   // 1024 warps: (b, word, tile-group) x 32 tiles
    render_kernel<<<BB*TILES_PER_B, 128>>>();
    loss_kernel<<<BB*HWPX/256, 256>>>(tgt_rgb, tgt_depth);
    finalize_kernel<<<1, 1>>>(out);
}

// round 8
// speedup vs baseline: 3.0248x; 1.2395x over previous
#include <cuda_runtime.h>
#include <math.h>

// Problem constants
#define BB 2
#define NN 1024
#define HH 128
#define WW 128
#define BN (BB*NN)
#define HWPX (HH*WW)

#define C0_SH 0.28209479177387814f
#define EXP_M10 4.5399929762484854e-05f   // exp(-10)
#define LOG2E 1.4426950408889634f
#define P2_CUT (-14.4269504f)             // -10 * log2(e)

// tiles: 8x4 pixels per warp-tile; 16 x 32 = 512 tiles per batch
#define TILES_PER_B 512
#define NWORDS 32                          // 1024 gaussians / 32
#define NSEG 4
#define SEG_LEN (NN/NSEG)                  // 256
#define SEG_WORDS (NWORDS/NSEG)            // 8

// mask kernel: one warp per (b, word, tile-group-of-32)
#define MASK_WARPS (BB*NWORDS*(TILES_PER_B/32))   // 2*32*16 = 1024
#define MASK_BLOCKS (MASK_WARPS*32/256)           // 128

// rank kernel: 8 segments of 128 gaussians per batch
#define RANK_SEGS 8

// ---------- scratch (no allocations allowed) ----------
__device__ float    g_par[BN*12];          // unsorted per-gaussian params
__device__ float4   g_sorted4[BN*3];       // z-sorted params, 3x float4 per gaussian
__device__ float4   g_geo[BN];             // sorted (px, py, R2, 0)
__device__ float    g_zkey[BN];
__device__ unsigned g_mask[BB*NWORDS*TILES_PER_B];   // [b][word][tile]
__device__ float4   g_pfxS[BB][NN+1];      // prefix color/depth aggregate
__device__ float    g_pfxP[BB][NN+1];      // prefix transmittance product
__device__ float    g_rgb[BB*3*HWPX];
__device__ float    g_depthimg[BB*HWPX];
__device__ double   g_acc[4];              // l1_rgb, ssim, l1_depth, opac_reg

// params layout per gaussian (12 floats):
// [0]=px [1]=py [2]=e0 [3]=e1 [4]=e2 [5]=cr [6]=cg [7]=cb [8]=z [9]=opac [10]=a0 [11]=R2

__global__ void zero_acc_kernel() {
    if (threadIdx.x < 4) g_acc[threadIdx.x] = 0.0;
}

__device__ __forceinline__ void block_reduce_to(double* target, float v, float* sdata) {
    int tid = threadIdx.x;
    sdata[tid] = v;
    __syncthreads();
    for (int s = blockDim.x >> 1; s > 0; s >>= 1) {
        if (tid < s) sdata[tid] += sdata[tid + s];
        __syncthreads();
    }
    if (tid == 0) atomicAdd(target, (double)sdata[0]);
}

// ---------- 1. per-gaussian preprocessing + opacity entropy ----------
__global__ void prep_kernel(const float* __restrict__ gs, const float* __restrict__ intr) {
    __shared__ float sred[256];
    int i = blockIdx.x * blockDim.x + threadIdx.x;
    int b = i / NN;
    const float* g = gs + (size_t)i * 38;

    float fx = intr[b*9 + 0], fy = intr[b*9 + 4];
    float cx = intr[b*9 + 2], cy = intr[b*9 + 5];

    float mx = g[0], my = g[1], mz = g[2];
    float sx = g[3], sy = g[4], sz = g[5];
    float qw = g[6], qx = g[7], qy = g[8], qz = g[9];
    float op = g[10];

    float z = fmaxf(mz, 1e-4f);
    float px = fx * mx / z + cx;
    float py = fy * my / z + cy;

    float R00 = 1.f - 2.f*(qy*qy + qz*qz);
    float R01 = 2.f*(qx*qy - qw*qz);
    float R02 = 2.f*(qx*qz + qw*qy);
    float R10 = 2.f*(qx*qy + qw*qz);
    float R11 = 1.f - 2.f*(qx*qx + qz*qz);
    float R12 = 2.f*(qy*qz - qw*qx);
    float R20 = 2.f*(qx*qz - qw*qy);
    float R21 = 2.f*(qy*qz + qw*qx);
    float R22 = 1.f - 2.f*(qx*qx + qy*qy);

    float RS00 = R00*sx, RS01 = R01*sy, RS02 = R02*sz;
    float RS10 = R10*sx, RS11 = R11*sy, RS12 = R12*sz;
    float RS20 = R20*sx, RS21 = R21*sy, RS22 = R22*sz;

    float zc  = fmaxf(mz, 1e-6f);
    float zsq = zc * zc;
    float J00 = fx / zc;
    float J02 = -fx * mx / zsq;
    float J11 = fy / zc;
    float J12 = -fy * my / zsq;

    float M00 = J00*RS00 + J02*RS20;
    float M01 = J00*RS01 + J02*RS21;
    float M02 = J00*RS02 + J02*RS22;
    float M10 = J11*RS10 + J12*RS20;
    float M11 = J11*RS11 + J12*RS21;
    float M12 = J11*RS12 + J12*RS22;

    float c00 = M00*M00 + M01*M01 + M02*M02 + 0.3f;
    float c01 = M00*M10 + M01*M11 + M02*M12;
    float c11 = M10*M10 + M11*M11 + M12*M12 + 0.3f;

    float detRaw = c00*c11 - c01*c01;
    float det = fmaxf(detRaw, 1e-8f);
    float inv00 = c11 / det;
    float inv11 = c00 / det;
    float inv01 = -c01 / det;

    // conic with folded -0.5*log2e (and the 2x on the cross term)
    float e0 = -0.5f * LOG2E * inv00;
    float e1 = -LOG2E * inv01;
    float e2 = -0.5f * LOG2E * inv11;

    // conservative cull radius: power < -10 guaranteed outside R
    float trC = c00 + c11;
    float discC = sqrtf(fmaxf(trC*trC - 4.f*detRaw, 0.f));
    float lmaxC = 0.5f * (trC + discC);
    float R2 = 20.f * lmaxC * 1.01f + 1.f;

    float cr = fminf(fmaxf(g[11]*C0_SH + 0.5f, 0.f), 1.f);
    float cg = fminf(fmaxf(g[12]*C0_SH + 0.5f, 0.f), 1.f);
    float cb = fminf(fmaxf(g[13]*C0_SH + 0.5f, 0.f), 1.f);

    float a0 = EXP_M10 * op;

    float* p = g_par + i*12;
    p[0]=px; p[1]=py; p[2]=e0; p[3]=e1; p[4]=e2;
    p[5]=cr; p[6]=cg; p[7]=cb; p[8]=z; p[9]=op; p[10]=a0; p[11]=R2;
    g_zkey[i] = z;

    float o = fminf(fmaxf(op, 1e-6f), 1.f - 1e-6f);
    float ent = -(o*logf(o) + (1.f-o)*logf(1.f-o));
    block_reduce_to(&g_acc[3], ent, sred);
}

// ---------- 2. rank-based stable sort + scatter ----------
// rank(i) = #{k: z_k < z_i} + #{k: z_k == z_i, k < i}  == stable argsort position
__global__ void __launch_bounds__(128) rank_kernel() {
    __shared__ float sz[NN];
    int b   = blockIdx.x / RANK_SEGS;
    int seg = blockIdx.x % RANK_SEGS;
    int li  = seg * 128 + threadIdx.x;        // index within batch
    int i   = b * NN + li;

    for (int k = threadIdx.x; k < NN; k += 128)
        sz[k] = g_zkey[b*NN + k];
    __syncthreads();

    float myz = sz[li];
    int rank = 0;
    #pragma unroll 8
    for (int k = 0; k < NN; k++) {
        float zk = sz[k];
        rank += (zk < myz) || (zk == myz && k < li);
    }

    const float* src = g_par + (size_t)i * 12;
    float* dst = (float*)(g_sorted4 + (size_t)(b*NN + rank) * 3);
    #pragma unroll
    for (int f = 0; f < 12; f++) dst[f] = src[f];
    g_geo[b*NN + rank] = make_float4(src[0], src[1], src[11], 0.f);
}

// ---------- 3. block-parallel prefix scan of far-field aggregates ----------
// monoid: (P,S) ∘ (p,s) = (P*p, S + P*s); element i: p=1-a0, s=a0*(c,z)
__global__ void __launch_bounds__(1024) scan_kernel() {
    __shared__ float sP[32];
    __shared__ float4 sS[32];
    int b = blockIdx.x;
    int tid = threadIdx.x;
    int lane = tid & 31, warp = tid >> 5;

    const float4* par = g_sorted4 + (size_t)b * NN * 3;
    float4 fb = par[tid*3+1];
    float4 fc = par[tid*3+2];
    float a0 = fc.z;

    float p = 1.f - a0;
    float sr = a0*fb.y, sg = a0*fb.z, sb = a0*fb.w, sd = a0*fc.x;

    // warp-inclusive scan
    #pragma unroll
    for (int off = 1; off < 32; off <<= 1) {
        float pp = __shfl_up_sync(0xffffffffu, p, off);
        float xr = __shfl_up_sync(0xffffffffu, sr, off);
        float xg = __shfl_up_sync(0xffffffffu, sg, off);
        float xb = __shfl_up_sync(0xffffffffu, sb, off);
        float xd = __shfl_up_sync(0xffffffffu, sd, off);
        if (lane >= off) {
            sr = xr + pp*sr; sg = xg + pp*sg; sb = xb + pp*sb; sd = xd + pp*sd;
            p = pp*p;
        }
    }
    if (lane == 31) { sP[warp] = p; sS[warp] = make_float4(sr, sg, sb, sd); }
    __syncthreads();

    // warp 0 scans the 32 warp totals -> exclusive warp prefixes
    if (warp == 0) {
        float wp = sP[lane];
        float4 wsv = sS[lane];
        float wr = wsv.x, wg2 = wsv.y, wb = wsv.z, wd = wsv.w;
        #pragma unroll
        for (int off = 1; off < 32; off <<= 1) {
            float pp = __shfl_up_sync(0xffffffffu, wp, off);
            float xr = __shfl_up_sync(0xffffffffu, wr, off);
            float xg = __shfl_up_sync(0xffffffffu, wg2, off);
            float xb = __shfl_up_sync(0xffffffffu, wb, off);
            float xd = __shfl_up_sync(0xffffffffu, wd, off);
            if (lane >= off) {
                wr = xr + pp*wr; wg2 = xg + pp*wg2; wb = xb + pp*wb; wd = xd + pp*wd;
                wp = pp*wp;
            }
        }
        // exclusive
        float ep = __shfl_up_sync(0xffffffffu, wp, 1);
        float er = __shfl_up_sync(0xffffffffu, wr, 1);
        float eg = __shfl_up_sync(0xffffffffu, wg2, 1);
        float eb = __shfl_up_sync(0xffffffffu, wb, 1);
        float ed = __shfl_up_sync(0xffffffffu, wd, 1);
        if (lane == 0) { ep = 1.f; er = eg = eb = ed = 0.f; }
        sP[lane] = ep; sS[lane] = make_float4(er, eg, eb, ed);
    }
    __syncthreads();

    float  Pw = sP[warp];
    float4 Sw = sS[warp];

    // exclusive lane prefix from inclusive
    float lp = __shfl_up_sync(0xffffffffu, p, 1);
    float lr = __shfl_up_sync(0xffffffffu, sr, 1);
    float lg = __shfl_up_sync(0xffffffffu, sg, 1);
    float lb = __shfl_up_sync(0xffffffffu, sb, 1);
    float ld = __shfl_up_sync(0xffffffffu, sd, 1);
    if (lane == 0) { lp = 1.f; lr = lg = lb = ld = 0.f; }

    // compose: warp prefix first, then lane prefix
    float  Pe = Pw * lp;
    float4 Se = make_float4(Sw.x + Pw*lr, Sw.y + Pw*lg, Sw.z + Pw*lb, Sw.w + Pw*ld);
    g_pfxP[b][tid] = Pe;
    g_pfxS[b][tid] = Se;

    if (tid == NN-1) {
        g_pfxP[b][NN] = Pw * p;
        g_pfxS[b][NN] = make_float4(Sw.x + Pw*sr, Sw.y + Pw*sg, Sw.z + Pw*sb, Sw.w + Pw*sd);
    }
}

// ---------- 4. per-tile activity bitmasks ----------
__global__ void mask_kernel() {
    int t = blockIdx.x * 256 + threadIdx.x;
    int gw = t >> 5, lane = t & 31;
    int b = gw >> 9;
    int rem = gw & 511;
    int word = rem >> 4;
    int grp = rem & 15;
    int tile = grp * 32 + lane;

    float x0 = (float)((tile & 15) * 8);
    float x1 = x0 + 7.f;
    float y0 = (float)((tile >> 4) * 4);
    float y1 = y0 + 3.f;

    const float4* geo = g_geo + (size_t)b * NN;
    unsigned m = 0;
    #pragma unroll 4
    for (int k = 0; k < 32; k++) {
        float4 ge = geo[word*32 + k];       // broadcast across warp
        float ex = fmaxf(fmaxf(x0 - ge.x, ge.x - x1), 0.f);
        float ey = fmaxf(fmaxf(y0 - ge.y, ge.y - y1), 0.f);
        if (ex*ex + ey*ey <= ge.z) m |= (1u << k);
    }
    g_mask[(b*NWORDS + word)*TILES_PER_B + tile] = m;
}

// ---------- 5. sparse compositing: warp=(tile, depth segment) ----------
__global__ void __launch_bounds__(128) render_kernel() {
    int b    = blockIdx.x >> 9;
    int tile = blockIdx.x & 511;
    int wid  = threadIdx.x >> 5;   // segment 0..3
    int lane = threadIdx.x & 31;

    int xpix = (tile & 15) * 8 + (lane & 7);
    int ypix = (tile >> 4) * 4 + (lane >> 3);
    float xf = (float)xpix, yf = (float)ypix;

    const float4* par = g_sorted4 + (size_t)b * NN * 3;
    const float4* Spfx = g_pfxS[b];
    const float*  Ppfx = g_pfxP[b];

    float T = 1.f, rr = 0.f, gg = 0.f, bbl = 0.f, dep = 0.f;
    int cur = wid * SEG_LEN;

    #pragma unroll 1
    for (int w = wid * SEG_WORDS; w < wid * SEG_WORDS + SEG_WORDS; w++) {
        unsigned m = g_mask[(b*NWORDS + w)*TILES_PER_B + tile];
        while (m) {
            int bit = __ffs(m) - 1;
            m &= m - 1;
            int j = (w << 5) + bit;
            if (j > cur) {   // culled run [cur, j): apply prefix aggregate
                float4 Si = Spfx[cur], Sj = Spfx[j];
                float f = __fdividef(T, Ppfx[cur]);
                rr  += f * (Sj.x - Si.x);
                gg  += f * (Sj.y - Si.y);
                bbl += f * (Sj.z - Si.z);
                dep += f * (Sj.w - Si.w);
                T = f * Ppfx[j];
            }
            // full evaluation of gaussian j
            float4 A  = par[j*3];
            float4 Bq = par[j*3+1];
            float4 Cq = par[j*3+2];
            float dx = xf - A.x, dy = yf - A.y;
            float p2 = A.z * dx * dx;
            p2 = fmaf(A.w, dx*dy, p2);
            p2 = fmaf(Bq.x, dy*dy, p2);
            p2 = fminf(p2, 0.f);
            float a;
            if (p2 > P2_CUT) {
                float e;
                asm("ex2.approx.ftz.f32 %0, %1;" : "=f"(e) : "f"(p2));
                a = fminf(e * Cq.y, 0.99f);
            } else {
                a = Cq.z;      // exp(-10)*opac
            }
            float wgt = T * a;
            rr  = fmaf(wgt, Bq.y, rr);
            gg  = fmaf(wgt, Bq.z, gg);
            bbl = fmaf(wgt, Bq.w, bbl);
            dep = fmaf(wgt, Cq.x, dep);
            T  -= wgt;
            cur = j + 1;
        }
    }
    int send = wid * SEG_LEN + SEG_LEN;
    if (cur < send) {
        float4 Si = Spfx[cur], Sj = Spfx[send];
        float f = __fdividef(T, Ppfx[cur]);
        rr  += f * (Sj.x - Si.x);
        gg  += f * (Sj.y - Si.y);
        bbl += f * (Sj.z - Si.z);
        dep += f * (Sj.w - Si.w);
        T = f * Ppfx[send];
    }

    // combine 4 depth segments (front-to-back)
    __shared__ float4 sC[NSEG][32];
    __shared__ float  sT[NSEG][32];
    sC[wid][lane] = make_float4(rr, gg, bbl, dep);
    sT[wid][lane] = T;
    __syncthreads();

    if (wid == 0) {
        float4 Cc = sC[0][lane];
        float  Tt = sT[0][lane];
        #pragma unroll
        for (int s = 1; s < NSEG; s++) {
            float4 Cs = sC[s][lane];
            Cc.x += Tt * Cs.x; Cc.y += Tt * Cs.y;
            Cc.z += Tt * Cs.z; Cc.w += Tt * Cs.w;
            Tt *= sT[s][lane];
        }
        int pix = ypix * WW + xpix;
        g_rgb[((size_t)(b*3 + 0))*HWPX + pix] = fminf(fmaxf(Cc.x, 0.f), 1.f);
        g_rgb[((size_t)(b*3 + 1))*HWPX + pix] = fminf(fmaxf(Cc.y, 0.f), 1.f);
        g_rgb[((size_t)(b*3 + 2))*HWPX + pix] = fminf(fmaxf(Cc.z, 0.f), 1.f);
        g_depthimg[(size_t)b*HWPX + pix] = Cc.w;
    }
}

// ---------- 6. SSIM + L1 losses ----------
__global__ void loss_kernel(const float* __restrict__ tgt_rgb,
                            const float* __restrict__ tgt_depth) {
    __shared__ float sred[256];
    int p   = blockIdx.x * 256 + threadIdx.x;
    int b   = p >> 14;
    int rem = p & 16383;
    int y   = rem >> 7;
    int x   = rem & 127;
    int pix = y*WW + x;

    float wg[7]; float ws = 0.f;
    #pragma unroll
    for (int i = 0; i < 7; i++) { float c = (float)(i-3); wg[i] = __expf(-c*c/4.5f); ws += wg[i]; }
    #pragma unroll
    for (int i = 0; i < 7; i++) wg[i] /= ws;

    const float SC1 = 1e-4f, SC2 = 9e-4f;

    float l1d = fabsf(g_depthimg[(size_t)b*HWPX + pix] - tgt_depth[(size_t)b*HWPX + pix]);

    float l1rgb = 0.f, ssim = 0.f;
    #pragma unroll
    for (int c = 0; c < 3; c++) {
        const float* im1 = g_rgb  + ((size_t)(b*3 + c))*HWPX;
        const float* im2 = tgt_rgb + ((size_t)(b*3 + c))*HWPX;
        l1rgb += fabsf(im1[pix] - im2[pix]);

        float mu1=0.f, mu2=0.f, e11=0.f, e22=0.f, e12=0.f;
        #pragma unroll
        for (int dy2 = -3; dy2 <= 3; dy2++) {
            int yy = y + dy2;
            if (yy < 0 || yy >= HH) continue;
            float wy = wg[dy2+3];
            #pragma unroll
            for (int dx2 = -3; dx2 <= 3; dx2++) {
                int xx = x + dx2;
                if (xx < 0 || xx >= WW) continue;
                float w = wy * wg[dx2+3];
                float a1 = im1[yy*WW + xx];
                float a2 = im2[yy*WW + xx];
                mu1 += w*a1; mu2 += w*a2;
                e11 += w*a1*a1; e22 += w*a2*a2; e12 += w*a1*a2;
            }
        }
        float s1  = e11 - mu1*mu1;
        float s2  = e22 - mu2*mu2;
        float s12 = e12 - mu1*mu2;
        ssim += (2.f*mu1*mu2 + SC1) * (2.f*s12 + SC2) /
                ((mu1*mu1 + mu2*mu2 + SC1) * (s1 + s2 + SC2));
    }

    block_reduce_to(&g_acc[0], l1rgb, sred);
    block_reduce_to(&g_acc[1], ssim,  sred);
    block_reduce_to(&g_acc[2], l1d,   sred);
}

// ---------- 7. final scalar ----------
__global__ void finalize_kernel(float* __restrict__ out) {
    double l1_rgb   = g_acc[0] / (double)(BB*3*HWPX);
    double ssim_val = g_acc[1] / (double)(BB*3*HWPX);
    double l1_depth = g_acc[2] / (double)(BB*HWPX);
    double opac_reg = g_acc[3] / (double)(BB*NN);
    out[0] = (float)(0.8*l1_rgb + 0.2*(1.0 - ssim_val) + 0.5*l1_depth + 0.01*opac_reg);
}

extern "C" void kernel_launch(void* const* d_in, const int* in_sizes, int n_in,
                              void* d_out, int out_size) {
    const float* gaussians = (const float*)d_in[0];
    const float* intr      = (const float*)d_in[1];
    const float* tgt_rgb   = (const float*)d_in[2];
    const float* tgt_depth = (const float*)d_in[3];
    float* out = (float*)d_out;

    zero_acc_kernel<<<1, 4>>>();
    prep_kernel<<<BN/256, 256>>>(gaussians, intr);
    rank_kernel<<<BB*RANK_SEGS, 128>>>();
    scan_kernel<<<BB, 1024>>>();
    mask_kernel<<<MASK_BLOCKS, 256>>>();
    render_kernel<<<BB*TILES_PER_B, 128>>>();
    loss_kernel<<<BB*HWPX/256, 256>>>(tgt_rgb, tgt_depth);
    finalize_kernel<<<1, 1>>>(out);
}